// round 3
// baseline (speedup 1.0000x reference)
#include <cuda_runtime.h>
#include <cuda_bf16.h>
#include <cstddef>

#define NN 100000
#define EE 1600000
#define ET 1700000   // EE + NN self loops

// ---------------- scratch (device globals; no allocation) ----------------
__device__ float g_h1[(size_t)NN * 64];     // layer-1 transformed features [N,64]
__device__ float g_asrc1[NN * 4];
__device__ float g_adst1[NN * 4];
__device__ float g_denom1[NN * 4];
__device__ float g_acc1[(size_t)NN * 64];   // layer-1 aggregation accumulator
__device__ float g_h2[NN];
__device__ float g_asrc2[NN];
__device__ float g_adst2[NN];
__device__ float g_denom2[NN];
__device__ float g_acc2[NN];

// ---------------- K0: zero accumulators ----------------
__global__ void k_zero() {
    size_t i = (size_t)blockIdx.x * blockDim.x + threadIdx.x;
    size_t stride = (size_t)gridDim.x * blockDim.x;
    for (size_t j = i; j < (size_t)NN * 64; j += stride) g_acc1[j] = 0.f;
    for (size_t j = i; j < (size_t)NN * 4;  j += stride) g_denom1[j] = 0.f;
    for (size_t j = i; j < (size_t)NN;      j += stride) { g_denom2[j] = 0.f; g_acc2[j] = 0.f; }
}

// ---------------- K1: h1 = x @ W1, plus attention dots ----------------
// 256 threads / block; block handles 64 nodes. Thread = (tx 0..15, ty 0..15),
// computes a 4-node x 4-channel tile. Channels j0..j0+3 lie in one head (16 | 4).
__global__ __launch_bounds__(256) void k_gemm1(const float* __restrict__ x,
                                               const float* __restrict__ W1,
                                               const float* __restrict__ att_s,
                                               const float* __restrict__ att_d) {
    __shared__ float Wsh[64 * 64];
    __shared__ float xsh[64 * 64];
    int t = threadIdx.x;
    int n0 = blockIdx.x * 64;

    for (int i = t; i < 4096; i += 256) Wsh[i] = W1[i];
    for (int i = t; i < 4096; i += 256) {
        int n = n0 + (i >> 6);
        xsh[i] = (n < NN) ? x[(size_t)n0 * 64 + i] : 0.f;
    }
    __syncthreads();

    int tx = t & 15, ty = t >> 4;
    int j0 = tx * 4;
    float acc[4][4];
#pragma unroll
    for (int i = 0; i < 4; i++)
#pragma unroll
        for (int q = 0; q < 4; q++) acc[i][q] = 0.f;

#pragma unroll 8
    for (int k = 0; k < 64; k++) {
        float4 w = *(const float4*)&Wsh[k * 64 + j0];
#pragma unroll
        for (int i = 0; i < 4; i++) {
            float xv = xsh[(ty * 4 + i) * 64 + k];
            acc[i][0] = fmaf(xv, w.x, acc[i][0]);
            acc[i][1] = fmaf(xv, w.y, acc[i][1]);
            acc[i][2] = fmaf(xv, w.z, acc[i][2]);
            acc[i][3] = fmaf(xv, w.w, acc[i][3]);
        }
    }

    // att_src1/att_dst1 are [4,16] flattened; flat index == channel index j
    float4 as = *(const float4*)&att_s[j0];
    float4 ad = *(const float4*)&att_d[j0];
    int head = tx >> 2;

#pragma unroll
    for (int i = 0; i < 4; i++) {
        int n = n0 + ty * 4 + i;
        if (n < NN) {
            float4 v = make_float4(acc[i][0], acc[i][1], acc[i][2], acc[i][3]);
            *(float4*)&g_h1[(size_t)n * 64 + j0] = v;
        }
        float ps = acc[i][0] * as.x + acc[i][1] * as.y + acc[i][2] * as.z + acc[i][3] * as.w;
        float pd = acc[i][0] * ad.x + acc[i][1] * ad.y + acc[i][2] * ad.z + acc[i][3] * ad.w;
        // reduce over the 4 threads sharing (node, head): tx bits 0,1
        ps += __shfl_xor_sync(0xffffffffu, ps, 1);
        ps += __shfl_xor_sync(0xffffffffu, ps, 2);
        pd += __shfl_xor_sync(0xffffffffu, pd, 1);
        pd += __shfl_xor_sync(0xffffffffu, pd, 2);
        if ((tx & 3) == 0 && n < NN) {
            g_asrc1[n * 4 + head] = ps;
            g_adst1[n * 4 + head] = pd;
        }
    }
}

// ---------------- K2: layer-1 edge pass (exp + denom + message scatter) ----------------
// One warp per edge. Softmax computed WITHOUT max-shift (shift-invariant; alpha bounded).
__global__ __launch_bounds__(256) void k_edge1(const int* __restrict__ ei) {
    int gw = (int)(((size_t)blockIdx.x * 256 + threadIdx.x) >> 5);
    int lane = threadIdx.x & 31;
    if (gw >= ET) return;

    int src, dst;
    if (gw < EE) { src = ei[gw]; dst = ei[EE + gw]; }
    else         { src = dst = gw - EE; }

    int h = lane & 3;
    float a = g_asrc1[src * 4 + h] + g_adst1[dst * 4 + h];
    a = a > 0.f ? a : 0.2f * a;          // leaky_relu, slope 0.2
    float myE = __expf(a);

    if (lane < 4) atomicAdd(&g_denom1[dst * 4 + lane], myE);

    // broadcast per-head exp values: channel c -> head c>>4
    float eA = __shfl_sync(0xffffffffu, myE, lane >> 4);        // heads 0,1
    float eB = __shfl_sync(0xffffffffu, myE, 2 + (lane >> 4));  // heads 2,3

    const float* hs = g_h1 + (size_t)src * 64;
    float* ac = g_acc1 + (size_t)dst * 64;
    atomicAdd(ac + lane,      hs[lane]      * eA);
    atomicAdd(ac + lane + 32, hs[lane + 32] * eB);
}

// ---------------- K3: finalize layer 1 (normalize + bias + ELU) and GEMM2 fused ----------------
// One warp per node; lane covers channels (lane, lane+32).
__global__ __launch_bounds__(256) void k_final1(const float* __restrict__ b1,
                                                const float* __restrict__ W2,
                                                const float* __restrict__ as2,
                                                const float* __restrict__ ad2) {
    int n = (int)(((size_t)blockIdx.x * 256 + threadIdx.x) >> 5);
    int lane = threadIdx.x & 31;
    if (n >= NN) return;

    float4 dnm = *(const float4*)&g_denom1[n * 4];
    float dA = (lane < 16) ? dnm.x : dnm.y;   // head of channel lane
    float dB = (lane < 16) ? dnm.z : dnm.w;   // head of channel lane+32

    float c0 = g_acc1[(size_t)n * 64 + lane];
    float c1 = g_acc1[(size_t)n * 64 + lane + 32];
    float o0 = c0 / (dA + 1e-16f) + b1[lane];
    float o1 = c1 / (dB + 1e-16f) + b1[lane + 32];
    o0 = o0 > 0.f ? o0 : expm1f(o0);          // ELU
    o1 = o1 > 0.f ? o1 : expm1f(o1);

    float p = o0 * W2[lane] + o1 * W2[lane + 32];
#pragma unroll
    for (int off = 16; off; off >>= 1) p += __shfl_xor_sync(0xffffffffu, p, off);

    if (lane == 0) {
        g_h2[n] = p;
        g_asrc2[n] = p * as2[0];
        g_adst2[n] = p * ad2[0];
    }
}

// ---------------- K4: layer-2 edge pass (1 head, 1 channel) ----------------
__global__ __launch_bounds__(256) void k_edge2(const int* __restrict__ ei) {
    int e = (int)((size_t)blockIdx.x * 256 + threadIdx.x);
    if (e >= ET) return;
    int src, dst;
    if (e < EE) { src = ei[e]; dst = ei[EE + e]; }
    else        { src = dst = e - EE; }
    float a = g_asrc2[src] + g_adst2[dst];
    a = a > 0.f ? a : 0.2f * a;
    float ee = __expf(a);
    atomicAdd(&g_denom2[dst], ee);
    atomicAdd(&g_acc2[dst], g_h2[src] * ee);
}

// ---------------- K5: final output ----------------
__global__ __launch_bounds__(256) void k_final2(float* __restrict__ out,
                                                const float* __restrict__ b2) {
    int n = (int)((size_t)blockIdx.x * 256 + threadIdx.x);
    if (n >= NN) return;
    out[n] = g_acc2[n] / (g_denom2[n] + 1e-16f) + b2[0];
}

// ---------------- launch ----------------
extern "C" void kernel_launch(void* const* d_in, const int* in_sizes, int n_in,
                              void* d_out, int out_size) {
    const float* x   = (const float*)d_in[0];
    const int*   ei  = (const int*)d_in[1];
    const float* W1  = (const float*)d_in[2];
    const float* as1 = (const float*)d_in[3];
    const float* ad1 = (const float*)d_in[4];
    const float* b1  = (const float*)d_in[5];
    const float* W2  = (const float*)d_in[6];
    const float* as2 = (const float*)d_in[7];
    const float* ad2 = (const float*)d_in[8];
    const float* b2  = (const float*)d_in[9];
    float* out = (float*)d_out;

    k_zero  <<<1024, 256>>>();
    k_gemm1 <<<(NN + 63) / 64, 256>>>(x, W1, as1, ad1);
    k_edge1 <<<(ET + 7) / 8, 256>>>(ei);          // 1 warp / edge
    k_final1<<<(NN + 7) / 8, 256>>>(b1, W2, as2, ad2);
    k_edge2 <<<(ET + 255) / 256, 256>>>(ei);
    k_final2<<<(NN + 255) / 256, 256>>>(out, b2);
}

// round 6
// speedup vs baseline: 1.0741x; 1.0741x over previous
#include <cuda_runtime.h>
#include <cuda_bf16.h>
#include <cstddef>

#define NN 100000
#define EE 1600000
#define ET 1700000   // EE + NN self loops
#define FULLM 0xffffffffu

// ---------------- scratch (device globals; no allocation) ----------------
__device__ float g_h1[(size_t)NN * 64];   // layer-1 transformed features [N,64]
__device__ float g_asrc1[NN * 4];
__device__ float g_adst1[NN * 4];
__device__ float g_h2[NN];
__device__ float g_asrc2[NN];
__device__ float g_adst2[NN];
// CSR (sorted-by-dst) structures
__device__ int g_cnt[NN];
__device__ int g_start[NN + 1];
__device__ int g_pos[NN];
__device__ int g_esrc[ET];

// ---------------- K0: zero degree counters ----------------
__global__ void k_zero_cnt() {
    int i = blockIdx.x * blockDim.x + threadIdx.x;
    if (i < NN) g_cnt[i] = 0;
}

// ---------------- K1: histogram of dst ----------------
__global__ __launch_bounds__(256) void k_hist(const int* __restrict__ ei) {
    int e = blockIdx.x * 256 + threadIdx.x;
    if (e >= ET) return;
    int dst = (e < EE) ? ei[EE + e] : (e - EE);
    atomicAdd(&g_cnt[dst], 1);
}

// ---------------- K2: single-block exclusive scan over counts ----------------
__global__ __launch_bounds__(1024) void k_scan() {
    __shared__ int sh[1024];
    const int T = 1024, CH = (NN + T - 1) / T;  // 98
    int t = threadIdx.x;
    int base = t * CH;
    int local = 0;
    for (int i = 0; i < CH; i++) {
        int idx = base + i;
        if (idx < NN) local += g_cnt[idx];
    }
    sh[t] = local;
    __syncthreads();
    for (int off = 1; off < T; off <<= 1) {
        int v = (t >= off) ? sh[t - off] : 0;
        __syncthreads();
        sh[t] += v;
        __syncthreads();
    }
    int run = (t == 0) ? 0 : sh[t - 1];
    for (int i = 0; i < CH; i++) {
        int idx = base + i;
        if (idx < NN) {
            int c = g_cnt[idx];
            g_start[idx] = run;
            g_pos[idx] = run;
            run += c;
        }
    }
    if (t == T - 1) g_start[NN] = run;
}

// ---------------- K3: scatter edge src ids into CSR slots ----------------
__global__ __launch_bounds__(256) void k_scatter(const int* __restrict__ ei) {
    int e = blockIdx.x * 256 + threadIdx.x;
    if (e >= ET) return;
    int src, dst;
    if (e < EE) { src = ei[e]; dst = ei[EE + e]; }
    else        { src = dst = e - EE; }
    int p = atomicAdd(&g_pos[dst], 1);
    g_esrc[p] = src;
}

// ---------------- K4: h1 = x @ W1, plus attention dots ----------------
__global__ __launch_bounds__(256) void k_gemm1(const float* __restrict__ x,
                                               const float* __restrict__ W1,
                                               const float* __restrict__ att_s,
                                               const float* __restrict__ att_d) {
    __shared__ float Wsh[64 * 64];
    __shared__ float xsh[64 * 64];
    int t = threadIdx.x;
    int n0 = blockIdx.x * 64;

    for (int i = t; i < 4096; i += 256) Wsh[i] = W1[i];
    for (int i = t; i < 4096; i += 256) {
        int n = n0 + (i >> 6);
        xsh[i] = (n < NN) ? x[(size_t)n0 * 64 + i] : 0.f;
    }
    __syncthreads();

    int tx = t & 15, ty = t >> 4;
    int j0 = tx * 4;
    float acc[4][4];
#pragma unroll
    for (int i = 0; i < 4; i++)
#pragma unroll
        for (int q = 0; q < 4; q++) acc[i][q] = 0.f;

#pragma unroll 8
    for (int k = 0; k < 64; k++) {
        float4 w = *(const float4*)&Wsh[k * 64 + j0];
#pragma unroll
        for (int i = 0; i < 4; i++) {
            float xv = xsh[(ty * 4 + i) * 64 + k];
            acc[i][0] = fmaf(xv, w.x, acc[i][0]);
            acc[i][1] = fmaf(xv, w.y, acc[i][1]);
            acc[i][2] = fmaf(xv, w.z, acc[i][2]);
            acc[i][3] = fmaf(xv, w.w, acc[i][3]);
        }
    }

    float4 as = *(const float4*)&att_s[j0];
    float4 ad = *(const float4*)&att_d[j0];
    int head = tx >> 2;

#pragma unroll
    for (int i = 0; i < 4; i++) {
        int n = n0 + ty * 4 + i;
        if (n < NN) {
            float4 v = make_float4(acc[i][0], acc[i][1], acc[i][2], acc[i][3]);
            *(float4*)&g_h1[(size_t)n * 64 + j0] = v;
        }
        float ps = acc[i][0] * as.x + acc[i][1] * as.y + acc[i][2] * as.z + acc[i][3] * as.w;
        float pd = acc[i][0] * ad.x + acc[i][1] * ad.y + acc[i][2] * ad.z + acc[i][3] * ad.w;
        ps += __shfl_xor_sync(FULLM, ps, 1);
        ps += __shfl_xor_sync(FULLM, ps, 2);
        pd += __shfl_xor_sync(FULLM, pd, 1);
        pd += __shfl_xor_sync(FULLM, pd, 2);
        if ((tx & 3) == 0 && n < NN) {
            g_asrc1[n * 4 + head] = ps;
            g_adst1[n * 4 + head] = pd;
        }
    }
}

// ---------------- K5: layer-1 gather-reduce, fused normalize+bias+ELU+GEMM2 ----------------
// One warp per dst node. Lane holds channels (lane, lane+32).
// Softmax computed WITHOUT max-shift (shift-invariant; alpha bounded ~|5|).
__global__ __launch_bounds__(256) void k_gather1(const float* __restrict__ b1,
                                                 const float* __restrict__ W2,
                                                 const float* __restrict__ as2,
                                                 const float* __restrict__ ad2) {
    int n = (blockIdx.x * 256 + threadIdx.x) >> 5;
    int lane = threadIdx.x & 31;
    if (n >= NN) return;

    int s = g_start[n], eend = g_start[n + 1];
    float4 ad = *(const float4*)&g_adst1[n * 4];   // broadcast across warp

    float acc0 = 0.f, acc1 = 0.f;
    float d0 = 0.f, d1 = 0.f, d2 = 0.f, d3 = 0.f;

    for (int base = s; base < eend; base += 32) {
        int j = base + lane;
        bool v = (j < eend);
        int sj = v ? g_esrc[j] : 0;
        float e0 = 0.f, e1 = 0.f, e2 = 0.f, e3 = 0.f;
        if (v) {
            float4 asv = *(const float4*)&g_asrc1[sj * 4];
            float a0 = asv.x + ad.x; a0 = a0 > 0.f ? a0 : 0.2f * a0; e0 = __expf(a0);
            float a1 = asv.y + ad.y; a1 = a1 > 0.f ? a1 : 0.2f * a1; e1 = __expf(a1);
            float a2 = asv.z + ad.z; a2 = a2 > 0.f ? a2 : 0.2f * a2; e2 = __expf(a2);
            float a3 = asv.w + ad.w; a3 = a3 > 0.f ? a3 : 0.2f * a3; e3 = __expf(a3);
            d0 += e0; d1 += e1; d2 += e2; d3 += e3;
        }
        int cnt = eend - base; if (cnt > 32) cnt = 32;
        for (int q = 0; q < cnt; q++) {
            int src = __shfl_sync(FULLM, sj, q);
            float f0 = __shfl_sync(FULLM, e0, q);
            float f1 = __shfl_sync(FULLM, e1, q);
            float f2 = __shfl_sync(FULLM, e2, q);
            float f3 = __shfl_sync(FULLM, e3, q);
            const float* hr = g_h1 + (size_t)src * 64;
            float eA = (lane < 16) ? f0 : f1;   // head of channel lane
            float eB = (lane < 16) ? f2 : f3;   // head of channel lane+32
            acc0 = fmaf(hr[lane],      eA, acc0);
            acc1 = fmaf(hr[lane + 32], eB, acc1);
        }
    }

    // warp-reduce denominators (per head)
#pragma unroll
    for (int off = 16; off; off >>= 1) {
        d0 += __shfl_xor_sync(FULLM, d0, off);
        d1 += __shfl_xor_sync(FULLM, d1, off);
        d2 += __shfl_xor_sync(FULLM, d2, off);
        d3 += __shfl_xor_sync(FULLM, d3, off);
    }
    float dA = (lane < 16) ? d0 : d1;
    float dB = (lane < 16) ? d2 : d3;

    float o0 = acc0 / (dA + 1e-16f) + b1[lane];
    float o1 = acc1 / (dB + 1e-16f) + b1[lane + 32];
    o0 = o0 > 0.f ? o0 : expm1f(o0);   // ELU
    o1 = o1 > 0.f ? o1 : expm1f(o1);

    float p = o0 * W2[lane] + o1 * W2[lane + 32];
#pragma unroll
    for (int off = 16; off; off >>= 1) p += __shfl_xor_sync(FULLM, p, off);

    if (lane == 0) {
        g_h2[n] = p;
        g_asrc2[n] = p * as2[0];
        g_adst2[n] = p * ad2[0];
    }
}

// ---------------- K6: layer-2 gather (1 head, 1 channel) + output ----------------
__global__ __launch_bounds__(256) void k_gather2(float* __restrict__ out,
                                                 const float* __restrict__ b2) {
    int n = (blockIdx.x * 256 + threadIdx.x) >> 5;
    int lane = threadIdx.x & 31;
    if (n >= NN) return;

    int s = g_start[n], eend = g_start[n + 1];
    float adn = g_adst2[n];
    float num = 0.f, den = 0.f;
    for (int j = s + lane; j < eend; j += 32) {
        int src = g_esrc[j];
        float a = g_asrc2[src] + adn;
        a = a > 0.f ? a : 0.2f * a;
        float e = __expf(a);
        den += e;
        num = fmaf(g_h2[src], e, num);
    }
#pragma unroll
    for (int off = 16; off; off >>= 1) {
        num += __shfl_xor_sync(FULLM, num, off);
        den += __shfl_xor_sync(FULLM, den, off);
    }
    if (lane == 0) out[n] = num / (den + 1e-16f) + b2[0];
}

// ---------------- launch ----------------
extern "C" void kernel_launch(void* const* d_in, const int* in_sizes, int n_in,
                              void* d_out, int out_size) {
    const float* x   = (const float*)d_in[0];
    const int*   ei  = (const int*)d_in[1];
    const float* W1  = (const float*)d_in[2];
    const float* as1 = (const float*)d_in[3];
    const float* ad1 = (const float*)d_in[4];
    const float* b1  = (const float*)d_in[5];
    const float* W2  = (const float*)d_in[6];
    const float* as2 = (const float*)d_in[7];
    const float* ad2 = (const float*)d_in[8];
    const float* b2  = (const float*)d_in[9];
    float* out = (float*)d_out;

    k_zero_cnt<<<(NN + 255) / 256, 256>>>();
    k_hist    <<<(ET + 255) / 256, 256>>>(ei);
    k_scan    <<<1, 1024>>>();
    k_scatter <<<(ET + 255) / 256, 256>>>(ei);
    k_gemm1   <<<(NN + 63) / 64, 256>>>(x, W1, as1, ad1);
    k_gather1 <<<(NN * 32 + 255) / 256, 256>>>(b1, W2, as2, ad2);
    k_gather2 <<<(NN * 32 + 255) / 256, 256>>>(out, b2);
}

// round 8
// speedup vs baseline: 1.1173x; 1.0403x over previous
#include <cuda_runtime.h>
#include <cuda_bf16.h>
#include <cstddef>

#define NN 100000
#define EE 1600000
#define ET 1700000   // EE + NN self loops
#define FULLM 0xffffffffu

// ---------------- scratch (device globals; no allocation) ----------------
__device__ float g_h1[(size_t)NN * 64];   // layer-1 transformed features [N,64]
__device__ float g_asrc1[NN * 4];
__device__ float g_adst1[NN * 4];
__device__ float2 g_p2[NN];               // {h2, asrc2} packed
__device__ float g_adst2[NN];
// CSR (sorted-by-dst) structures
__device__ int g_cnt[NN];
__device__ int g_start[NN + 1];
__device__ int g_pos[NN];
__device__ int g_esrc[ET];

// ---------------- K0: init degree counters to 1 (self-loop pre-counted) ----------------
__global__ void k_init_cnt() {
    int i = blockIdx.x * blockDim.x + threadIdx.x;
    if (i < NN) g_cnt[i] = 1;
}

// ---------------- K1: histogram of dst (4 edges/thread, int4) ----------------
__global__ __launch_bounds__(256) void k_hist(const int* __restrict__ ei) {
    int t = blockIdx.x * 256 + threadIdx.x;
    if (t >= EE / 4) return;
    int4 d = ((const int4*)(ei + EE))[t];
    atomicAdd(&g_cnt[d.x], 1);
    atomicAdd(&g_cnt[d.y], 1);
    atomicAdd(&g_cnt[d.z], 1);
    atomicAdd(&g_cnt[d.w], 1);
}

// ---------------- K2: single-block exclusive scan over counts ----------------
__global__ __launch_bounds__(1024) void k_scan() {
    __shared__ int sh[1024];
    const int T = 1024, CH = (NN + T - 1) / T;  // 98
    int t = threadIdx.x;
    int base = t * CH;
    int local = 0;
    for (int i = 0; i < CH; i++) {
        int idx = base + i;
        if (idx < NN) local += g_cnt[idx];
    }
    sh[t] = local;
    __syncthreads();
    for (int off = 1; off < T; off <<= 1) {
        int v = (t >= off) ? sh[t - off] : 0;
        __syncthreads();
        sh[t] += v;
        __syncthreads();
    }
    int run = (t == 0) ? 0 : sh[t - 1];
    for (int i = 0; i < CH; i++) {
        int idx = base + i;
        if (idx < NN) {
            int c = g_cnt[idx];
            g_start[idx] = run;
            g_pos[idx] = run;
            run += c;
        }
    }
    if (t == T - 1) g_start[NN] = run;
}

// ---------------- K3: scatter edge src ids into CSR slots (4 edges/thread) ----------------
__global__ __launch_bounds__(256) void k_scatter(const int* __restrict__ ei) {
    int t = blockIdx.x * 256 + threadIdx.x;
    const int REAL = EE / 4;                 // 400000
    if (t < REAL) {
        int4 s = ((const int4*)ei)[t];
        int4 d = ((const int4*)(ei + EE))[t];
        int p0 = atomicAdd(&g_pos[d.x], 1);
        int p1 = atomicAdd(&g_pos[d.y], 1);
        int p2 = atomicAdd(&g_pos[d.z], 1);
        int p3 = atomicAdd(&g_pos[d.w], 1);
        g_esrc[p0] = s.x; g_esrc[p1] = s.y; g_esrc[p2] = s.z; g_esrc[p3] = s.w;
    } else {
        int b = (t - REAL) * 4;
#pragma unroll
        for (int k = 0; k < 4; k++) {
            int n = b + k;
            if (n < NN) {
                int p = atomicAdd(&g_pos[n], 1);
                g_esrc[p] = n;
            }
        }
    }
}

// ---------------- K4: h1 = x @ W1, plus attention dots ----------------
__global__ __launch_bounds__(256) void k_gemm1(const float* __restrict__ x,
                                               const float* __restrict__ W1,
                                               const float* __restrict__ att_s,
                                               const float* __restrict__ att_d) {
    __shared__ float Wsh[64 * 64];
    __shared__ float xsh[64 * 64];
    int t = threadIdx.x;
    int n0 = blockIdx.x * 64;

    for (int i = t; i < 4096; i += 256) Wsh[i] = W1[i];
    for (int i = t; i < 4096; i += 256) {
        int n = n0 + (i >> 6);
        xsh[i] = (n < NN) ? x[(size_t)n0 * 64 + i] : 0.f;
    }
    __syncthreads();

    int tx = t & 15, ty = t >> 4;
    int j0 = tx * 4;
    float acc[4][4];
#pragma unroll
    for (int i = 0; i < 4; i++)
#pragma unroll
        for (int q = 0; q < 4; q++) acc[i][q] = 0.f;

#pragma unroll 4
    for (int k4 = 0; k4 < 64; k4 += 4) {
        float4 xv[4];
#pragma unroll
        for (int i = 0; i < 4; i++)
            xv[i] = *(const float4*)&xsh[(ty * 4 + i) * 64 + k4];
#pragma unroll
        for (int kk = 0; kk < 4; kk++) {
            float4 w = *(const float4*)&Wsh[(k4 + kk) * 64 + j0];
#pragma unroll
            for (int i = 0; i < 4; i++) {
                float xvk = ((const float*)&xv[i])[kk];
                acc[i][0] = fmaf(xvk, w.x, acc[i][0]);
                acc[i][1] = fmaf(xvk, w.y, acc[i][1]);
                acc[i][2] = fmaf(xvk, w.z, acc[i][2]);
                acc[i][3] = fmaf(xvk, w.w, acc[i][3]);
            }
        }
    }

    float4 as = *(const float4*)&att_s[j0];
    float4 ad = *(const float4*)&att_d[j0];
    int head = tx >> 2;

#pragma unroll
    for (int i = 0; i < 4; i++) {
        int n = n0 + ty * 4 + i;
        if (n < NN) {
            float4 v = make_float4(acc[i][0], acc[i][1], acc[i][2], acc[i][3]);
            *(float4*)&g_h1[(size_t)n * 64 + j0] = v;
        }
        float ps = acc[i][0] * as.x + acc[i][1] * as.y + acc[i][2] * as.z + acc[i][3] * as.w;
        float pd = acc[i][0] * ad.x + acc[i][1] * ad.y + acc[i][2] * ad.z + acc[i][3] * ad.w;
        ps += __shfl_xor_sync(FULLM, ps, 1);
        ps += __shfl_xor_sync(FULLM, ps, 2);
        pd += __shfl_xor_sync(FULLM, pd, 1);
        pd += __shfl_xor_sync(FULLM, pd, 2);
        if ((tx & 3) == 0 && n < NN) {
            g_asrc1[n * 4 + head] = ps;
            g_adst1[n * 4 + head] = pd;
        }
    }
}

// ---------------- K5: layer-1 gather-reduce, fused normalize+bias+ELU+GEMM2 ----------------
// One warp per dst node; lane holds channels (lane, lane+32).
// Staged smem + x4 unroll for MLP. Softmax WITHOUT max-shift (shift-invariant).
__global__ __launch_bounds__(256) void k_gather1(const float* __restrict__ b1,
                                                 const float* __restrict__ W2,
                                                 const float* __restrict__ as2,
                                                 const float* __restrict__ ad2) {
    __shared__ int    s_src[8][32];
    __shared__ float2 s_ee[8][2][32];   // [warp][laneHalf][slot] = {eA, eB}
    int wIn = threadIdx.x >> 5;
    int lane = threadIdx.x & 31;
    int n = blockIdx.x * 8 + wIn;
    if (n >= NN) return;

    int s = g_start[n], eend = g_start[n + 1];
    float4 ad = *(const float4*)&g_adst1[n * 4];

    float acc0 = 0.f, acc1 = 0.f;
    float d0 = 0.f, d1 = 0.f, d2 = 0.f, d3 = 0.f;

    const float2* ep = s_ee[wIn][lane >= 16 ? 1 : 0];

    for (int base = s; base < eend; base += 32) {
        int j = base + lane;
        bool v = (j < eend);
        int sj = v ? g_esrc[j] : 0;
        float e0 = 0.f, e1 = 0.f, e2 = 0.f, e3 = 0.f;
        if (v) {
            float4 asv = *(const float4*)&g_asrc1[sj * 4];
            float a0 = asv.x + ad.x; a0 = a0 > 0.f ? a0 : 0.2f * a0; e0 = __expf(a0);
            float a1 = asv.y + ad.y; a1 = a1 > 0.f ? a1 : 0.2f * a1; e1 = __expf(a1);
            float a2 = asv.z + ad.z; a2 = a2 > 0.f ? a2 : 0.2f * a2; e2 = __expf(a2);
            float a3 = asv.w + ad.w; a3 = a3 > 0.f ? a3 : 0.2f * a3; e3 = __expf(a3);
            d0 += e0; d1 += e1; d2 += e2; d3 += e3;
        }
        s_src[wIn][lane] = sj;
        s_ee[wIn][0][lane] = make_float2(e0, e2);   // lanes 0-15: heads (0,2)
        s_ee[wIn][1][lane] = make_float2(e1, e3);   // lanes 16-31: heads (1,3)
        __syncwarp();

        int cnt = eend - base; if (cnt > 32) cnt = 32;
        int q = 0;
        for (; q + 4 <= cnt; q += 4) {
            int sq0 = s_src[wIn][q + 0];
            int sq1 = s_src[wIn][q + 1];
            int sq2 = s_src[wIn][q + 2];
            int sq3 = s_src[wIn][q + 3];
            const float* h0 = g_h1 + (size_t)sq0 * 64;
            const float* h1 = g_h1 + (size_t)sq1 * 64;
            const float* h2 = g_h1 + (size_t)sq2 * 64;
            const float* h3 = g_h1 + (size_t)sq3 * 64;
            float v00 = h0[lane], v01 = h0[lane + 32];
            float v10 = h1[lane], v11 = h1[lane + 32];
            float v20 = h2[lane], v21 = h2[lane + 32];
            float v30 = h3[lane], v31 = h3[lane + 32];
            float2 q0 = ep[q + 0], q1 = ep[q + 1], q2 = ep[q + 2], q3 = ep[q + 3];
            acc0 = fmaf(v00, q0.x, acc0); acc1 = fmaf(v01, q0.y, acc1);
            acc0 = fmaf(v10, q1.x, acc0); acc1 = fmaf(v11, q1.y, acc1);
            acc0 = fmaf(v20, q2.x, acc0); acc1 = fmaf(v21, q2.y, acc1);
            acc0 = fmaf(v30, q3.x, acc0); acc1 = fmaf(v31, q3.y, acc1);
        }
        for (; q < cnt; q++) {
            int sq = s_src[wIn][q];
            const float* hr = g_h1 + (size_t)sq * 64;
            float2 eq = ep[q];
            acc0 = fmaf(hr[lane],      eq.x, acc0);
            acc1 = fmaf(hr[lane + 32], eq.y, acc1);
        }
        __syncwarp();
    }

    // warp-reduce denominators (per head)
#pragma unroll
    for (int off = 16; off; off >>= 1) {
        d0 += __shfl_xor_sync(FULLM, d0, off);
        d1 += __shfl_xor_sync(FULLM, d1, off);
        d2 += __shfl_xor_sync(FULLM, d2, off);
        d3 += __shfl_xor_sync(FULLM, d3, off);
    }
    float dA = (lane < 16) ? d0 : d1;
    float dB = (lane < 16) ? d2 : d3;

    float o0 = acc0 / (dA + 1e-16f) + b1[lane];
    float o1 = acc1 / (dB + 1e-16f) + b1[lane + 32];
    o0 = o0 > 0.f ? o0 : expm1f(o0);   // ELU
    o1 = o1 > 0.f ? o1 : expm1f(o1);

    float p = o0 * W2[lane] + o1 * W2[lane + 32];
#pragma unroll
    for (int off = 16; off; off >>= 1) p += __shfl_xor_sync(FULLM, p, off);

    if (lane == 0) {
        g_p2[n] = make_float2(p, p * as2[0]);   // {h2, asrc2}
        g_adst2[n] = p * ad2[0];
    }
}

// ---------------- K6: layer-2 gather (1 head, 1 channel) + output ----------------
__global__ __launch_bounds__(256) void k_gather2(float* __restrict__ out,
                                                 const float* __restrict__ b2) {
    int n = (blockIdx.x * 256 + threadIdx.x) >> 5;
    int lane = threadIdx.x & 31;
    if (n >= NN) return;

    int s = g_start[n], eend = g_start[n + 1];
    float adn = g_adst2[n];
    float num = 0.f, den = 0.f;
    for (int j = s + lane; j < eend; j += 32) {
        int src = g_esrc[j];
        float2 hs = g_p2[src];          // {h2, asrc2} one 8B load
        float a = hs.y + adn;
        a = a > 0.f ? a : 0.2f * a;
        float e = __expf(a);
        den += e;
        num = fmaf(hs.x, e, num);
    }
#pragma unroll
    for (int off = 16; off; off >>= 1) {
        num += __shfl_xor_sync(FULLM, num, off);
        den += __shfl_xor_sync(FULLM, den, off);
    }
    if (lane == 0) out[n] = num / (den + 1e-16f) + b2[0];
}

// ---------------- launch ----------------
extern "C" void kernel_launch(void* const* d_in, const int* in_sizes, int n_in,
                              void* d_out, int out_size) {
    const float* x   = (const float*)d_in[0];
    const int*   ei  = (const int*)d_in[1];
    const float* W1  = (const float*)d_in[2];
    const float* as1 = (const float*)d_in[3];
    const float* ad1 = (const float*)d_in[4];
    const float* b1  = (const float*)d_in[5];
    const float* W2  = (const float*)d_in[6];
    const float* as2 = (const float*)d_in[7];
    const float* ad2 = (const float*)d_in[8];
    const float* b2  = (const float*)d_in[9];
    float* out = (float*)d_out;

    const int SCAT_T = EE / 4 + (NN + 3) / 4;   // 425000
    k_init_cnt<<<(NN + 255) / 256, 256>>>();
    k_hist    <<<(EE / 4 + 255) / 256, 256>>>(ei);
    k_scan    <<<1, 1024>>>();
    k_scatter <<<(SCAT_T + 255) / 256, 256>>>(ei);
    k_gemm1   <<<(NN + 63) / 64, 256>>>(x, W1, as1, ad1);
    k_gather1 <<<(NN + 7) / 8, 256>>>(b1, W2, as2, ad2);
    k_gather2 <<<(NN * 32 + 255) / 256, 256>>>(out, b2);
}